// round 12
// baseline (speedup 1.0000x reference)
#include <cuda_runtime.h>
#include <math.h>

#define NBOX 1024
#define EPSF 1e-8f
#define NMS_TH 0.1f
#define MAXSP (1<<16)
#define MAXOV 4096
#define GRID 148
#define TPB 1024
#define NTH (GRID*TPB)
#define FULLM 0xFFFFFFFFu
#define CAP_J 256
#define CAP_C 128

struct Box {
    float cx, cy, hx, hy, cs, sn;
    float corx[4], cory[4];
    float rad, zmin, zmax, area, vol;
    float pad;
};

__device__ Box g_gt[NBOX];
__device__ Box g_pred[NBOX];
__device__ float4 g_qgt[NBOX];     // cx, cy, rad, zmin
__device__ float4 g_qpred[NBOX];
__device__ float g_zmaxgt[NBOX];
__device__ float g_zmaxpred[NBOX];
__device__ unsigned g_key[NBOX];
__device__ int g_order[NBOX];
__device__ int g_pos[NBOX];
__device__ int g_keep_orig[NBOX];
__device__ int g_cnt_sp;
__device__ int g_cnt_ov;
__device__ unsigned g_sp[MAXSP];             // orig-space suppression pairs
__device__ unsigned g_ovf_row[MAXOV];        // pg candidate overflow
__device__ unsigned long long g_ovf_pack[MAXOV];
__device__ unsigned long long g_rowbest[NBOX];

__device__ unsigned g_bar_arrive;
__device__ volatile unsigned g_bar_release;

__device__ __forceinline__ void gbar() {
    __syncthreads();
    if (threadIdx.x == 0) {
        __threadfence();
        unsigned t = atomicAdd(&g_bar_arrive, 1u) + 1u;
        unsigned need = ((t + GRID - 1u) / GRID) * GRID;
        if (t == need) g_bar_release = need;
        else while (g_bar_release < need) { }
        __threadfence();
    }
    __syncthreads();
}

// ---------------------------------------------------------------------------
// Rotated-rect intersection — bit-identical to the passing R1 math.
// ---------------------------------------------------------------------------
__device__ float inter_area(const Box& a, const Box& b) {
    float px[24], py[24];
    int k = 0;

#pragma unroll
    for (int q = 0; q < 4; q++) {
        float dxp = a.corx[q] - b.cx, dyp = a.cory[q] - b.cy;
        float lx =  dxp * b.cs + dyp * b.sn;
        float ly = -dxp * b.sn + dyp * b.cs;
        if (fabsf(lx) <= b.hx + 1e-5f && fabsf(ly) <= b.hy + 1e-5f) {
            px[k] = a.corx[q]; py[k] = a.cory[q]; k++;
        }
    }
#pragma unroll
    for (int q = 0; q < 4; q++) {
        float dxp = b.corx[q] - a.cx, dyp = b.cory[q] - a.cy;
        float lx =  dxp * a.cs + dyp * a.sn;
        float ly = -dxp * a.sn + dyp * a.cs;
        if (fabsf(lx) <= a.hx + 1e-5f && fabsf(ly) <= a.hy + 1e-5f) {
            px[k] = b.corx[q]; py[k] = b.cory[q]; k++;
        }
    }
#pragma unroll
    for (int p = 0; p < 4; p++) {
        float a0x = a.corx[p], a0y = a.cory[p];
        float a1x = a.corx[(p + 1) & 3], a1y = a.cory[(p + 1) & 3];
        float d1x = a1x - a0x, d1y = a1y - a0y;
#pragma unroll
        for (int q = 0; q < 4; q++) {
            float b0x = b.corx[q], b0y = b.cory[q];
            float b1x = b.corx[(q + 1) & 3], b1y = b.cory[(q + 1) & 3];
            float d2x = b1x - b0x, d2y = b1y - b0y;
            float r0x = b0x - a0x, r0y = b0y - a0y;
            float den = d1x * d2y - d1y * d2x;
            if (fabsf(den) > EPSF) {
                float t = (r0x * d2y - r0y * d2x) / den;
                float u = (r0x * d1y - r0y * d1x) / den;
                if (t >= 0.f && t <= 1.f && u >= 0.f && u <= 1.f) {
                    px[k] = a0x + t * d1x;
                    py[k] = a0y + t * d1y;
                    k++;
                }
            }
        }
    }

    if (k < 3) return 0.f;

    float sx = 0.f, sy = 0.f;
    for (int i = 0; i < k; i++) { sx += px[i]; sy += py[i]; }
    float fk = (float)k;
    float cxm = sx / fk, cym = sy / fk;

    float ang[24];
    for (int i = 0; i < k; i++) {
        px[i] -= cxm; py[i] -= cym;
        ang[i] = atan2f(py[i], px[i]);
    }
    for (int i = 1; i < k; i++) {
        float ax = px[i], ay = py[i], aa = ang[i];
        int j = i - 1;
        while (j >= 0 && ang[j] > aa) {
            px[j + 1] = px[j]; py[j + 1] = py[j]; ang[j + 1] = ang[j];
            j--;
        }
        px[j + 1] = ax; py[j + 1] = ay; ang[j + 1] = aa;
    }
    float s = 0.f;
    for (int i = 0; i < k; i++) {
        int j = (i + 1 == k) ? 0 : (i + 1);
        s += px[i] * py[j] - py[i] * px[j];
    }
    return 0.5f * fabsf(s);
}

// ---------------------------------------------------------------------------
__global__ __launch_bounds__(TPB, 1)
void mega_kernel(const float* __restrict__ labels,
                 const float* __restrict__ pred_boxes,
                 const float* __restrict__ gt_boxes,
                 const float* __restrict__ cls,
                 float* __restrict__ out) {
    extern __shared__ unsigned s_mem[];
    // blocks > 0: per-warp scratch (block 0 reuses all 128KB as scan matrix)
    unsigned* s_jlist = s_mem;                                        // [32][CAP_J]
    unsigned long long* s_cand = (unsigned long long*)(s_mem + 8192); // [32][CAP_C]
    unsigned* s_ccnt = s_mem + 16384;                                 // [32]

    const int tid = threadIdx.x;
    const int bid = blockIdx.x;
    const int wid = tid >> 5;
    const int lane = tid & 31;
    const int gtid = bid * TPB + tid;
    const unsigned lt = (1u << lane) - 1u;

    // ================= Phase A: init + per-box precompute ==================
    if (gtid == 0) { g_cnt_sp = 0; g_cnt_ov = 0; }
    if (gtid < NBOX) {
        g_rowbest[gtid] = 0xFFFFFFFFull;   // iou=0, idx=0
        float lab = labels[gtid];
        unsigned u = __float_as_uint(lab);
        g_key[gtid] = (u & 0x80000000u) ? ~u : (u | 0x80000000u);
        float sgm = 1.0f / (1.0f + expf(-cls[gtid]));
        out[gtid] = (sgm > 0.55f && lab > 0.55f) ? 1.0f : 0.0f;
        out[NBOX + gtid] = lab;
    }
    for (int t = gtid; t < 2 * NBOX; t += NTH) {
        bool isgt = (t < NBOX);
        int i = isgt ? t : t - NBOX;
        const float* p = isgt ? (gt_boxes + i * 8) : (pred_boxes + i * 7);
        Box b;
        b.cx = p[0]; b.cy = p[1];
        float z = p[2], dx = p[3], dy = p[4], dz = p[5], r = p[6];
        b.hx = 0.5f * dx; b.hy = 0.5f * dy;
        float csn = cosf(r), snn = sinf(r);
        b.cs = csn; b.sn = snn;
        const float sxt[4] = {1.f, 1.f, -1.f, -1.f};
        const float syt[4] = {1.f, -1.f, -1.f, 1.f};
#pragma unroll
        for (int q = 0; q < 4; q++) {
            float lx = sxt[q] * b.hx, ly = syt[q] * b.hy;
            b.corx[q] = lx * csn - ly * snn + b.cx;
            b.cory[q] = lx * snn + ly * csn + b.cy;
        }
        b.rad = sqrtf(b.hx * b.hx + b.hy * b.hy) + 5e-4f;
        b.zmin = z - dz * 0.5f;
        b.zmax = z + dz * 0.5f;
        b.area = dx * dy;
        b.vol = dx * dy * dz;
        b.pad = 0.f;
        if (isgt) {
            g_gt[i] = b;
            g_qgt[i] = make_float4(b.cx, b.cy, b.rad, b.zmin);
            g_zmaxgt[i] = b.zmax;
        } else {
            g_pred[i] = b;
            g_qpred[i] = make_float4(b.cx, b.cy, b.rad, b.zmin);
            g_zmaxpred[i] = b.zmax;
        }
    }
    gbar();

    // === Phase B: block0 zeros scan matrix; others: rank / gg / pg rows ====
    const int r = (bid - 1) * 32 + wid;   // row task id for blocks >= 1
    int my_ccnt = 0;                      // pg candidate count (warp-uniform)

    if (bid == 0) {
        for (int t = tid; t < NBOX * 32; t += TPB) s_mem[t] = 0u;
    } else if (r < NBOX) {
        // ---- rank row: stable descending rank of key[r] ----
        unsigned ki = g_key[r];
        int cnt = 0;
        for (int j = lane; j < NBOX; j += 32) {
            unsigned kj = g_key[j];
            cnt += (kj > ki) || (kj == ki && j < r);
        }
#pragma unroll
        for (int o = 16; o > 0; o >>= 1) cnt += __shfl_down_sync(FULLM, cnt, o);
        if (lane == 0) { g_pos[r] = cnt; g_order[cnt] = r; }
    } else if (r < 2 * NBOX) {
        // ---- gg row: fused prune + heavy + suppression-pair emit ----
        int i = r - NBOX;
        float4 qi = g_qgt[i];
        int cnt = 0;
        unsigned jbase = (unsigned)wid * CAP_J;
        for (int chunk = 0; chunk < NBOX; chunk += 32) {
            int j = chunk + lane;
            bool pass = false;
            if (j > i) {
                float4 qj = g_qgt[j];
                float ddx = qi.x - qj.x, ddy = qi.y - qj.y;
                float rr = qi.z + qj.z;
                pass = (ddx * ddx + ddy * ddy <= rr * rr);
            }
            unsigned m = __ballot_sync(FULLM, pass);
            if (pass) s_jlist[jbase + cnt + __popc(m & lt)] = (unsigned)j;
            cnt += __popc(m);
            bool flush = (cnt >= CAP_J - 32) || (chunk + 32 >= NBOX);
            if (flush && cnt > 0) {
                int ngrp = (cnt + 31) / 32;
                for (int g = 0; g < ngrp; g++) {
                    int idx = g * 32 + lane;
                    bool act = (idx < cnt);
                    int j2 = act ? (int)s_jlist[jbase + idx] : 0;
                    bool sup = false;
                    if (act) {
                        float inter = inter_area(g_gt[i], g_gt[j2]);
                        float iou = inter /
                            fmaxf(g_gt[i].area + g_gt[j2].area - inter, EPSF);
                        sup = (iou > NMS_TH);
                    }
                    unsigned sm = __ballot_sync(FULLM, sup);
                    if (sm) {
                        int leader = __ffs(sm) - 1;
                        int base = 0;
                        if (lane == leader) base = atomicAdd(&g_cnt_sp, __popc(sm));
                        base = __shfl_sync(FULLM, base, leader);
                        if (sup) {
                            int d = base + __popc(sm & lt);
                            if (d < MAXSP)
                                g_sp[d] = ((unsigned)i << 10) | (unsigned)j2;
                        }
                    }
                }
                cnt = 0;
            }
        }
    } else if (r < 3 * NBOX) {
        // ---- pg row: fused prune + heavy; candidates stay in warp smem ----
        int i = r - 2 * NBOX;
        float4 qi = g_qpred[i];
        float zmaxi = g_zmaxpred[i];
        int cnt = 0;
        unsigned jbase = (unsigned)wid * CAP_J;
        unsigned cbase = (unsigned)wid * CAP_C;
        for (int chunk = 0; chunk < NBOX; chunk += 32) {
            int j = chunk + lane;
            float4 qj = g_qgt[j];
            float oh0 = fminf(zmaxi, g_zmaxgt[j]) - fmaxf(qi.w, qj.w);
            float ddx = qi.x - qj.x, ddy = qi.y - qj.y;
            float rr = qi.z + qj.z;
            bool pass = (oh0 > 0.f) && (ddx * ddx + ddy * ddy <= rr * rr);
            unsigned m = __ballot_sync(FULLM, pass);
            if (pass) s_jlist[jbase + cnt + __popc(m & lt)] = (unsigned)j;
            cnt += __popc(m);
            bool flush = (cnt >= CAP_J - 32) || (chunk + 32 >= NBOX);
            if (flush && cnt > 0) {
                int ngrp = (cnt + 31) / 32;
                for (int g = 0; g < ngrp; g++) {
                    int idx = g * 32 + lane;
                    bool act = (idx < cnt);
                    int j2 = act ? (int)s_jlist[jbase + idx] : 0;
                    unsigned long long pack = 0ull;
                    bool store = false;
                    if (act) {
                        const Box& a = g_pred[i];
                        const Box& b = g_gt[j2];
                        float inter = inter_area(a, b);
                        float oh = fmaxf(fminf(a.zmax, b.zmax) -
                                         fmaxf(a.zmin, b.zmin), 0.f);
                        float i3 = inter * oh;
                        float iou = i3 / fmaxf(a.vol + b.vol - i3, EPSF);
                        if (iou > 0.f) {
                            pack = ((unsigned long long)__float_as_uint(iou) << 32)
                                 | (unsigned long long)(0xFFFFFFFFu - (unsigned)j2);
                            store = true;
                        }
                    }
                    unsigned m2 = __ballot_sync(FULLM, store);
                    int base = my_ccnt + __popc(m2 & lt);
                    if (store && base < CAP_C) s_cand[cbase + base] = pack;
                    unsigned ovm = __ballot_sync(FULLM, store && base >= CAP_C);
                    if (ovm) {
                        int leader = __ffs(ovm) - 1;
                        int ob = 0;
                        if (lane == leader) ob = atomicAdd(&g_cnt_ov, __popc(ovm));
                        ob = __shfl_sync(FULLM, ob, leader);
                        if (store && base >= CAP_C) {
                            int d = ob + __popc(ovm & lt);
                            if (d < MAXOV) {
                                g_ovf_row[d] = (unsigned)i;
                                g_ovf_pack[d] = pack;
                            }
                        }
                    }
                    my_ccnt += __popc(m2);
                }
                cnt = 0;
            }
        }
        if (lane == 0) s_ccnt[wid] = (unsigned)my_ccnt;
    }
    gbar();

    // ====== Phase C (block 0): scatter supp pairs into smem -> NMS scan =====
    if (bid == 0) {
        int nsp = *(volatile int*)&g_cnt_sp; if (nsp > MAXSP) nsp = MAXSP;
        for (int t = tid; t < nsp; t += TPB) {
            unsigned pr = g_sp[t];
            int i = pr >> 10, j = pr & 1023;
            int a = g_pos[i], b = g_pos[j];
            int lo = min(a, b), hi = max(a, b);
            atomicOr(&s_mem[lo * 32 + (hi >> 5)], 1u << (hi & 31));
        }
        __syncthreads();
        if (tid < 32) {
            unsigned keep = FULLM;
            for (int w = 0; w < 32; w++) {
                unsigned kcur = __shfl_sync(FULLM, keep, w);
                unsigned mdiaw = s_mem[(w * 32 + lane) * 32 + w];
                unsigned conf = __ballot_sync(FULLM,
                    ((kcur >> lane) & 1u) && (mdiaw & kcur));
                if (conf == 0) {
                    unsigned bits = kcur;
                    while (bits) {
                        int u = __ffs(bits) - 1; bits &= bits - 1;
                        keep &= ~s_mem[(w * 32 + u) * 32 + lane];
                    }
                } else {
                    unsigned kc = kcur;
                    while (kc) {
                        int u = __ffs(kc) - 1;
                        unsigned mdia_u = __shfl_sync(FULLM, mdiaw, u);
                        keep &= ~s_mem[(w * 32 + u) * 32 + lane];
                        kc = (kc & (kc - 1)) & ~mdia_u;
                    }
                }
            }
#pragma unroll
            for (int b = 0; b < 32; b++) {
                int a = lane * 32 + b;
                g_keep_orig[g_order[a]] = (int)((keep >> b) & 1u);
            }
        }
    }
    gbar();

    // ====== Phase D: keep-filter + reduce (same warp, data still in smem) ===
    if (bid > 0 && r >= 2 * NBOX && r < 3 * NBOX) {
        int i = r - 2 * NBOX;
        int cc = (int)s_ccnt[wid]; if (cc > CAP_C) cc = CAP_C;
        unsigned long long best = 0xFFFFFFFFull;
        unsigned cbase = (unsigned)wid * CAP_C;
        for (int t = lane; t < cc; t += 32) {
            unsigned long long p = s_cand[cbase + t];
            int j = (int)(0xFFFFFFFFu - (unsigned)p);
            if (g_keep_orig[j] && p > best) best = p;
        }
#pragma unroll
        for (int o = 16; o > 0; o >>= 1) {
            unsigned long long q = __shfl_down_sync(FULLM, best, o);
            if (q > best) best = q;
        }
        if (lane == 0) atomicMax(&g_rowbest[i], best);
    }
    {   // overflow candidates (normally zero)
        int nov = *(volatile int*)&g_cnt_ov; if (nov > MAXOV) nov = MAXOV;
        for (int t = gtid; t < nov; t += NTH) {
            unsigned long long p = g_ovf_pack[t];
            int j = (int)(0xFFFFFFFFu - (unsigned)p);
            if (g_keep_orig[j]) atomicMax(&g_rowbest[g_ovf_row[t]], p);
        }
    }
    gbar();

    // ======================= Phase E: finalize output ======================
    if (gtid < NBOX) {
        unsigned long long b = *((volatile unsigned long long*)&g_rowbest[gtid]);
        float v = __uint_as_float((unsigned)(b >> 32));
        unsigned idx = 0xFFFFFFFFu - (unsigned)(b & 0xFFFFFFFFull);
        float mo = (v > 0.75f) ? 1.0f : ((v < 0.25f) ? 0.0f : v);
        out[2 * NBOX + gtid] = mo;
        out[3 * NBOX + gtid] = (float)idx;
    }
}

// ---------------------------------------------------------------------------
extern "C" void kernel_launch(void* const* d_in, const int* in_sizes, int n_in,
                              void* d_out, int out_size) {
    const float* labels = (const float*)d_in[0];
    const float* pred   = (const float*)d_in[1];
    const float* gt     = (const float*)d_in[2];
    const float* cls    = (const float*)d_in[3];
    for (int i = 0; i < n_in; i++) {
        if (in_sizes[i] == NBOX * 7) pred = (const float*)d_in[i];
        else if (in_sizes[i] == NBOX * 8) gt = (const float*)d_in[i];
    }
    float* out = (float*)d_out;

    cudaFuncSetAttribute(mega_kernel,
                         cudaFuncAttributeMaxDynamicSharedMemorySize, 131072);
    mega_kernel<<<GRID, TPB, 131072>>>(labels, pred, gt, cls, out);
}

// round 17
// speedup vs baseline: 1.1468x; 1.1468x over previous
#include <cuda_runtime.h>
#include <math.h>

#define NBOX 1024
#define EPSF 1e-8f
#define NMS_TH 0.1f
#define MAXSP (1<<16)
#define MAXOV 4096
#define FULLM 0xFFFFFFFFu
#define CAP_J 256
#define CAP_C 160

struct Box {
    float cx, cy, hx, hy, cs, sn;
    float corx[4], cory[4];
    float rad, zmin, zmax, area, vol;
    float pad;
};

__device__ Box g_gt[NBOX];
__device__ Box g_pred[NBOX];
__device__ float4 g_qgt[NBOX];     // cx, cy, rad, zmin
__device__ float4 g_qpred[NBOX];
__device__ float g_zmaxgt[NBOX];
__device__ float g_zmaxpred[NBOX];
__device__ unsigned g_key[NBOX];
__device__ int g_order[NBOX];
__device__ int g_pos[NBOX];
__device__ int g_keep_orig[NBOX];
__device__ int g_cnt_sp;
__device__ int g_cnt_ov;
__device__ unsigned g_sp[MAXSP];                  // orig-space suppression pairs
__device__ unsigned g_ovf_row[MAXOV];
__device__ unsigned long long g_ovf_pack[MAXOV];
__device__ unsigned long long g_cand[NBOX * CAP_C];  // per-pred-row candidates
__device__ int g_ccnt[NBOX];

// ---------------------------------------------------------------------------
// Rotated-rect intersection — bit-identical to the passing R1 math.
// ---------------------------------------------------------------------------
__device__ float inter_area(const Box& a, const Box& b) {
    float px[24], py[24];
    int k = 0;

#pragma unroll
    for (int q = 0; q < 4; q++) {
        float dxp = a.corx[q] - b.cx, dyp = a.cory[q] - b.cy;
        float lx =  dxp * b.cs + dyp * b.sn;
        float ly = -dxp * b.sn + dyp * b.cs;
        if (fabsf(lx) <= b.hx + 1e-5f && fabsf(ly) <= b.hy + 1e-5f) {
            px[k] = a.corx[q]; py[k] = a.cory[q]; k++;
        }
    }
#pragma unroll
    for (int q = 0; q < 4; q++) {
        float dxp = b.corx[q] - a.cx, dyp = b.cory[q] - a.cy;
        float lx =  dxp * a.cs + dyp * a.sn;
        float ly = -dxp * a.sn + dyp * a.cs;
        if (fabsf(lx) <= a.hx + 1e-5f && fabsf(ly) <= a.hy + 1e-5f) {
            px[k] = b.corx[q]; py[k] = b.cory[q]; k++;
        }
    }
#pragma unroll
    for (int p = 0; p < 4; p++) {
        float a0x = a.corx[p], a0y = a.cory[p];
        float a1x = a.corx[(p + 1) & 3], a1y = a.cory[(p + 1) & 3];
        float d1x = a1x - a0x, d1y = a1y - a0y;
#pragma unroll
        for (int q = 0; q < 4; q++) {
            float b0x = b.corx[q], b0y = b.cory[q];
            float b1x = b.corx[(q + 1) & 3], b1y = b.cory[(q + 1) & 3];
            float d2x = b1x - b0x, d2y = b1y - b0y;
            float r0x = b0x - a0x, r0y = b0y - a0y;
            float den = d1x * d2y - d1y * d2x;
            if (fabsf(den) > EPSF) {
                float t = (r0x * d2y - r0y * d2x) / den;
                float u = (r0x * d1y - r0y * d1x) / den;
                if (t >= 0.f && t <= 1.f && u >= 0.f && u <= 1.f) {
                    px[k] = a0x + t * d1x;
                    py[k] = a0y + t * d1y;
                    k++;
                }
            }
        }
    }

    if (k < 3) return 0.f;

    float sx = 0.f, sy = 0.f;
    for (int i = 0; i < k; i++) { sx += px[i]; sy += py[i]; }
    float fk = (float)k;
    float cxm = sx / fk, cym = sy / fk;

    float ang[24];
    for (int i = 0; i < k; i++) {
        px[i] -= cxm; py[i] -= cym;
        ang[i] = atan2f(py[i], px[i]);
    }
    for (int i = 1; i < k; i++) {
        float ax = px[i], ay = py[i], aa = ang[i];
        int j = i - 1;
        while (j >= 0 && ang[j] > aa) {
            px[j + 1] = px[j]; py[j + 1] = py[j]; ang[j + 1] = ang[j];
            j--;
        }
        px[j + 1] = ax; py[j + 1] = ay; ang[j + 1] = aa;
    }
    float s = 0.f;
    for (int i = 0; i < k; i++) {
        int j = (i + 1 == k) ? 0 : (i + 1);
        s += px[i] * py[j] - py[i] * px[j];
    }
    return 0.5f * fabsf(s);
}

// ======================== K1: init + per-box precompute =====================
__global__ __launch_bounds__(256)
void k_prep(const float* __restrict__ labels,
            const float* __restrict__ pred_boxes,
            const float* __restrict__ gt_boxes,
            const float* __restrict__ cls,
            float* __restrict__ out) {
    int gtid = blockIdx.x * 256 + threadIdx.x;   // 4096 threads
    if (gtid == 0) { g_cnt_sp = 0; g_cnt_ov = 0; }
    if (gtid < NBOX) {
        float lab = labels[gtid];
        unsigned u = __float_as_uint(lab);
        g_key[gtid] = (u & 0x80000000u) ? ~u : (u | 0x80000000u);
        float sgm = 1.0f / (1.0f + expf(-cls[gtid]));
        out[gtid] = (sgm > 0.55f && lab > 0.55f) ? 1.0f : 0.0f;
        out[NBOX + gtid] = lab;
    }
    for (int t = gtid; t < 2 * NBOX; t += 4096) {
        bool isgt = (t < NBOX);
        int i = isgt ? t : t - NBOX;
        const float* p = isgt ? (gt_boxes + i * 8) : (pred_boxes + i * 7);
        Box b;
        b.cx = p[0]; b.cy = p[1];
        float z = p[2], dx = p[3], dy = p[4], dz = p[5], r = p[6];
        b.hx = 0.5f * dx; b.hy = 0.5f * dy;
        float csn = cosf(r), snn = sinf(r);
        b.cs = csn; b.sn = snn;
        const float sxt[4] = {1.f, 1.f, -1.f, -1.f};
        const float syt[4] = {1.f, -1.f, -1.f, 1.f};
#pragma unroll
        for (int q = 0; q < 4; q++) {
            float lx = sxt[q] * b.hx, ly = syt[q] * b.hy;
            b.corx[q] = lx * csn - ly * snn + b.cx;
            b.cory[q] = lx * snn + ly * csn + b.cy;
        }
        b.rad = sqrtf(b.hx * b.hx + b.hy * b.hy) + 5e-4f;
        b.zmin = z - dz * 0.5f;
        b.zmax = z + dz * 0.5f;
        b.area = dx * dy;
        b.vol = dx * dy * dz;
        b.pad = 0.f;
        if (isgt) {
            g_gt[i] = b;
            g_qgt[i] = make_float4(b.cx, b.cy, b.rad, b.zmin);
            g_zmaxgt[i] = b.zmax;
        } else {
            g_pred[i] = b;
            g_qpred[i] = make_float4(b.cx, b.cy, b.rad, b.zmin);
            g_zmaxpred[i] = b.zmax;
        }
    }
}

// ============ K2: one warp per row — rank / gg-fused / pg-fused =============
__global__ __launch_bounds__(1024, 1)
void k_pairwise() {
    __shared__ unsigned s_jlist[32 * CAP_J];
    const int tid = threadIdx.x;
    const int wid = tid >> 5;
    const int lane = tid & 31;
    const unsigned lt = (1u << lane) - 1u;
    const int r = blockIdx.x * 32 + wid;          // 96 blocks * 32 warps = 3072

    if (r < NBOX) {
        // ---- rank row: stable descending rank of key[r] ----
        unsigned ki = g_key[r];
        int cnt = 0;
        for (int j = lane; j < NBOX; j += 32) {
            unsigned kj = g_key[j];
            cnt += (kj > ki) || (kj == ki && j < r);
        }
#pragma unroll
        for (int o = 16; o > 0; o >>= 1) cnt += __shfl_down_sync(FULLM, cnt, o);
        if (lane == 0) { g_pos[r] = cnt; g_order[cnt] = r; }
    } else if (r < 2 * NBOX) {
        // ---- gg row: fused prune + heavy + suppression-pair emit ----
        int i = r - NBOX;
        float4 qi = g_qgt[i];
        int cnt = 0;
        unsigned jbase = (unsigned)wid * CAP_J;
        for (int chunk = 0; chunk < NBOX; chunk += 32) {
            int j = chunk + lane;
            bool pass = false;
            if (j > i) {
                float4 qj = g_qgt[j];
                float ddx = qi.x - qj.x, ddy = qi.y - qj.y;
                float rr = qi.z + qj.z;
                pass = (ddx * ddx + ddy * ddy <= rr * rr);
            }
            unsigned m = __ballot_sync(FULLM, pass);
            if (pass) s_jlist[jbase + cnt + __popc(m & lt)] = (unsigned)j;
            cnt += __popc(m);
            bool flush = (cnt >= CAP_J - 32) || (chunk + 32 >= NBOX);
            if (flush && cnt > 0) {
                int ngrp = (cnt + 31) / 32;
                for (int g = 0; g < ngrp; g++) {
                    int idx = g * 32 + lane;
                    bool act = (idx < cnt);
                    int j2 = act ? (int)s_jlist[jbase + idx] : 0;
                    bool sup = false;
                    if (act) {
                        float inter = inter_area(g_gt[i], g_gt[j2]);
                        float iou = inter /
                            fmaxf(g_gt[i].area + g_gt[j2].area - inter, EPSF);
                        sup = (iou > NMS_TH);
                    }
                    unsigned sm = __ballot_sync(FULLM, sup);
                    if (sm) {
                        int leader = __ffs(sm) - 1;
                        int base = 0;
                        if (lane == leader) base = atomicAdd(&g_cnt_sp, __popc(sm));
                        base = __shfl_sync(FULLM, base, leader);
                        if (sup) {
                            int d = base + __popc(sm & lt);
                            if (d < MAXSP)
                                g_sp[d] = ((unsigned)i << 10) | (unsigned)j2;
                        }
                    }
                }
                cnt = 0;
            }
        }
    } else {
        // ---- pg row: fused prune + heavy -> per-row candidate slots ----
        int i = r - 2 * NBOX;
        float4 qi = g_qpred[i];
        float zmaxi = g_zmaxpred[i];
        int cnt = 0, ccnt = 0;
        unsigned jbase = (unsigned)wid * CAP_J;
        unsigned cbase = (unsigned)i * CAP_C;
        for (int chunk = 0; chunk < NBOX; chunk += 32) {
            int j = chunk + lane;
            float4 qj = g_qgt[j];
            float oh0 = fminf(zmaxi, g_zmaxgt[j]) - fmaxf(qi.w, qj.w);
            float ddx = qi.x - qj.x, ddy = qi.y - qj.y;
            float rr = qi.z + qj.z;
            bool pass = (oh0 > 0.f) && (ddx * ddx + ddy * ddy <= rr * rr);
            unsigned m = __ballot_sync(FULLM, pass);
            if (pass) s_jlist[jbase + cnt + __popc(m & lt)] = (unsigned)j;
            cnt += __popc(m);
            bool flush = (cnt >= CAP_J - 32) || (chunk + 32 >= NBOX);
            if (flush && cnt > 0) {
                int ngrp = (cnt + 31) / 32;
                for (int g = 0; g < ngrp; g++) {
                    int idx = g * 32 + lane;
                    bool act = (idx < cnt);
                    int j2 = act ? (int)s_jlist[jbase + idx] : 0;
                    unsigned long long pack = 0ull;
                    bool store = false;
                    if (act) {
                        const Box& a = g_pred[i];
                        const Box& b = g_gt[j2];
                        float inter = inter_area(a, b);
                        float oh = fmaxf(fminf(a.zmax, b.zmax) -
                                         fmaxf(a.zmin, b.zmin), 0.f);
                        float i3 = inter * oh;
                        float iou = i3 / fmaxf(a.vol + b.vol - i3, EPSF);
                        if (iou > 0.f) {
                            pack = ((unsigned long long)__float_as_uint(iou) << 32)
                                 | (unsigned long long)(0xFFFFFFFFu - (unsigned)j2);
                            store = true;
                        }
                    }
                    unsigned m2 = __ballot_sync(FULLM, store);
                    int base = ccnt + __popc(m2 & lt);
                    if (store && base < CAP_C) g_cand[cbase + base] = pack;
                    unsigned ovm = __ballot_sync(FULLM, store && base >= CAP_C);
                    if (ovm) {
                        int leader = __ffs(ovm) - 1;
                        int ob = 0;
                        if (lane == leader) ob = atomicAdd(&g_cnt_ov, __popc(ovm));
                        ob = __shfl_sync(FULLM, ob, leader);
                        if (store && base >= CAP_C) {
                            int d = ob + __popc(ovm & lt);
                            if (d < MAXOV) {
                                g_ovf_row[d] = (unsigned)i;
                                g_ovf_pack[d] = pack;
                            }
                        }
                    }
                    ccnt += __popc(m2);
                }
                cnt = 0;
            }
        }
        if (lane == 0) g_ccnt[i] = (ccnt < CAP_C) ? ccnt : CAP_C;
    }
}

// ======== K3 (1 block): zero smem matrix -> scatter -> warp NMS scan ========
__global__ __launch_bounds__(1024, 1)
void k_scan() {
    extern __shared__ unsigned s_mat[];           // 128KB
    const int tid = threadIdx.x;
    const int lane = tid & 31;
    for (int t = tid; t < NBOX * 32; t += 1024) s_mat[t] = 0u;
    __syncthreads();
    int nsp = g_cnt_sp; if (nsp > MAXSP) nsp = MAXSP;
    for (int t = tid; t < nsp; t += 1024) {
        unsigned pr = g_sp[t];
        int i = pr >> 10, j = pr & 1023;
        int a = g_pos[i], b = g_pos[j];
        int lo = min(a, b), hi = max(a, b);
        atomicOr(&s_mat[lo * 32 + (hi >> 5)], 1u << (hi & 31));
    }
    __syncthreads();
    if (tid < 32) {
        unsigned keep = FULLM;
        for (int w = 0; w < 32; w++) {
            unsigned kcur = __shfl_sync(FULLM, keep, w);
            unsigned mdiaw = s_mat[(w * 32 + lane) * 32 + w];
            unsigned conf = __ballot_sync(FULLM,
                ((kcur >> lane) & 1u) && (mdiaw & kcur));
            if (conf == 0) {
                unsigned bits = kcur;
                while (bits) {
                    int u = __ffs(bits) - 1; bits &= bits - 1;
                    keep &= ~s_mat[(w * 32 + u) * 32 + lane];
                }
            } else {
                unsigned kc = kcur;
                while (kc) {
                    int u = __ffs(kc) - 1;
                    unsigned mdia_u = __shfl_sync(FULLM, mdiaw, u);
                    keep &= ~s_mat[(w * 32 + u) * 32 + lane];
                    kc = (kc & (kc - 1)) & ~mdia_u;
                }
            }
        }
#pragma unroll
        for (int b = 0; b < 32; b++) {
            int a = lane * 32 + b;
            g_keep_orig[g_order[a]] = (int)((keep >> b) & 1u);
        }
    }
}

// ===== K4: warp per pred row — keep-filter + reduce + write output ==========
__global__ __launch_bounds__(1024, 1)
void k_final(float* __restrict__ out) {
    const int tid = threadIdx.x;
    const int wid = tid >> 5;
    const int lane = tid & 31;
    const int i = blockIdx.x * 32 + wid;          // 32 blocks * 32 warps = 1024
    if (i >= NBOX) return;
    int cc = g_ccnt[i];
    unsigned long long best = 0xFFFFFFFFull;      // iou=0, idx=0
    unsigned cbase = (unsigned)i * CAP_C;
    for (int t = lane; t < cc; t += 32) {
        unsigned long long p = g_cand[cbase + t];
        int j = (int)(0xFFFFFFFFu - (unsigned)p);
        if (g_keep_orig[j] && p > best) best = p;
    }
    int nov = g_cnt_ov; if (nov > MAXOV) nov = MAXOV;
    for (int t = lane; t < nov; t += 32) {        // rare path, normally 0
        if (g_ovf_row[t] == (unsigned)i) {
            unsigned long long p = g_ovf_pack[t];
            int j = (int)(0xFFFFFFFFu - (unsigned)p);
            if (g_keep_orig[j] && p > best) best = p;
        }
    }
#pragma unroll
    for (int o = 16; o > 0; o >>= 1) {
        unsigned long long q = __shfl_down_sync(FULLM, best, o);
        if (q > best) best = q;
    }
    if (lane == 0) {
        float v = __uint_as_float((unsigned)(best >> 32));
        unsigned idx = 0xFFFFFFFFu - (unsigned)(best & 0xFFFFFFFFull);
        float mo = (v > 0.75f) ? 1.0f : ((v < 0.25f) ? 0.0f : v);
        out[2 * NBOX + i] = mo;
        out[3 * NBOX + i] = (float)idx;
    }
}

// ---------------------------------------------------------------------------
extern "C" void kernel_launch(void* const* d_in, const int* in_sizes, int n_in,
                              void* d_out, int out_size) {
    const float* labels = (const float*)d_in[0];
    const float* pred   = (const float*)d_in[1];
    const float* gt     = (const float*)d_in[2];
    const float* cls    = (const float*)d_in[3];
    for (int i = 0; i < n_in; i++) {
        if (in_sizes[i] == NBOX * 7) pred = (const float*)d_in[i];
        else if (in_sizes[i] == NBOX * 8) gt = (const float*)d_in[i];
    }
    float* out = (float*)d_out;

    cudaFuncSetAttribute(k_scan,
                         cudaFuncAttributeMaxDynamicSharedMemorySize, 131072);
    k_prep<<<16, 256>>>(labels, pred, gt, cls, out);
    k_pairwise<<<96, 1024>>>();
    k_scan<<<1, 1024, 131072>>>();
    k_final<<<32, 1024>>>(out);
}